// round 4
// baseline (speedup 1.0000x reference)
#include <cuda_runtime.h>
#include <math.h>

// Problem dims
#define NB 2
#define NN 512
#define CSD 384
#define NH 12
#define NC 16
#define NP 8
#define NPV 8
#define NK 16
#define NG 64
#define HC (NH*NC)          // 192
#define HPV3 (NH*NPV*3)     // 288

// Packed f32x2 FMA (Blackwell, PTX-only)
#define FFMA2(d, a, b, c) \
    asm("fma.rn.f32x2 %0, %1, %2, %3;" : "=l"(d) : "l"(a), "l"(b), "l"(c))
#define UNPACK2(lo, hi, v) \
    asm("mov.b64 {%0, %1}, %2;" : "=f"(lo), "=f"(hi) : "l"(v))

// ---------------- scratch (device globals) -------------
__device__ __align__(16) float g_q   [NB*NN*HC];
__device__ __align__(16) float g_k   [NB*NN*HC];
__device__ __align__(16) float g_v   [NB*NN*HC];
__device__ __align__(16) float g_qpts[NB*NN*NP*3];
__device__ __align__(16) float g_vpts[NB*NN*NP*3];
__device__ __align__(16) float g_vg  [NB*NN*HPV3];
__device__ __align__(16) float g_logits[(size_t)NB*NH*NN*NN];
__device__ __align__(16) float g_o   [NB*NN*HC];
__device__ __align__(16) float g_opt [NB*NN*HPV3];

// ================= K1: per-row projections, 8 rows per block =================
#define K1R 8
__global__ void k1_project(const float* __restrict__ s,
                           const float* __restrict__ rot,
                           const float* __restrict__ trans,
                           const float* __restrict__ Wq,  const float* __restrict__ bq,
                           const float* __restrict__ Wkv, const float* __restrict__ bkv,
                           const float* __restrict__ ln_g,const float* __restrict__ ln_b,
                           const float* __restrict__ Wpq, const float* __restrict__ bpq,
                           const float* __restrict__ Wpv, const float* __restrict__ bpv,
                           const float* __restrict__ Wkvp,const float* __restrict__ bkvp)
{
    __shared__ float ssh [K1R*CSD];
    __shared__ float snsh[K1R*CSD];
    __shared__ float kvpsh[K1R*HPV3];

    int bn0 = blockIdx.x * K1R;
    int tid = threadIdx.x;
    int wid = tid >> 5, lane = tid & 31;

    for (int idx = tid; idx < K1R*CSD; idx += blockDim.x)
        ssh[idx] = s[(size_t)bn0 * CSD + idx];
    __syncthreads();

    {
        int r = wid;
        const float* row = ssh + r * CSD;
        float lsum = 0.f;
        for (int i = lane; i < CSD; i += 32) lsum += row[i];
        #pragma unroll
        for (int o = 16; o > 0; o >>= 1) lsum += __shfl_xor_sync(0xffffffffu, lsum, o);
        float mean = lsum * (1.0f / CSD);
        float lvar = 0.f;
        for (int i = lane; i < CSD; i += 32) { float d = row[i] - mean; lvar += d * d; }
        #pragma unroll
        for (int o = 16; o > 0; o >>= 1) lvar += __shfl_xor_sync(0xffffffffu, lvar, o);
        float inv = rsqrtf(lvar * (1.0f / CSD) + 1e-5f);
        for (int i = lane; i < CSD; i += 32)
            snsh[r * CSD + i] = (row[i] - mean) * inv * ln_g[i] + ln_b[i];
    }
    __syncthreads();

    for (int col = tid; col < 912; col += blockDim.x) {
        float acc[K1R];
        if (col < HC) {
            #pragma unroll
            for (int r = 0; r < K1R; r++) acc[r] = bq[col];
            for (int cs = 0; cs < CSD; cs++) {
                float w = Wq[(size_t)cs * HC + col];
                #pragma unroll
                for (int r = 0; r < K1R; r++) acc[r] += ssh[r*CSD+cs] * w;
            }
            #pragma unroll
            for (int r = 0; r < K1R; r++) g_q[(size_t)(bn0+r) * HC + col] = acc[r];
        } else if (col < 3*HC) {
            int j2 = col - HC;
            #pragma unroll
            for (int r = 0; r < K1R; r++) acc[r] = bkv[j2];
            for (int cs = 0; cs < CSD; cs++) {
                float w = Wkv[(size_t)cs * (2*HC) + j2];
                #pragma unroll
                for (int r = 0; r < K1R; r++) acc[r] += ssh[r*CSD+cs] * w;
            }
            int h = j2 >> 5, rr = j2 & 31;
            #pragma unroll
            for (int r = 0; r < K1R; r++) {
                if (rr < NC) g_k[(size_t)(bn0+r) * HC + h * NC + rr] = acc[r];
                else         g_v[(size_t)(bn0+r) * HC + h * NC + (rr - NC)] = acc[r];
            }
        } else if (col < 600) {
            int c2 = col - 576;
            #pragma unroll
            for (int r = 0; r < K1R; r++) acc[r] = bpq[c2];
            for (int cs = 0; cs < CSD; cs++) {
                float w = Wpq[(size_t)cs * (NP*3) + c2];
                #pragma unroll
                for (int r = 0; r < K1R; r++) acc[r] += snsh[r*CSD+cs] * w;
            }
            #pragma unroll
            for (int r = 0; r < K1R; r++) g_qpts[(size_t)(bn0+r) * (NP*3) + c2] = acc[r];
        } else if (col < 624) {
            int c2 = col - 600;
            #pragma unroll
            for (int r = 0; r < K1R; r++) acc[r] = bpv[c2];
            for (int cs = 0; cs < CSD; cs++) {
                float w = Wpv[(size_t)cs * (NP*3) + c2];
                #pragma unroll
                for (int r = 0; r < K1R; r++) acc[r] += snsh[r*CSD+cs] * w;
            }
            #pragma unroll
            for (int r = 0; r < K1R; r++) g_vpts[(size_t)(bn0+r) * (NP*3) + c2] = acc[r];
        } else {
            int c2 = col - 624;
            #pragma unroll
            for (int r = 0; r < K1R; r++) acc[r] = bkvp[c2];
            for (int cs = 0; cs < CSD; cs++) {
                float w = Wkvp[(size_t)cs * HPV3 + c2];
                #pragma unroll
                for (int r = 0; r < K1R; r++) acc[r] += ssh[r*CSD+cs] * w;
            }
            #pragma unroll
            for (int r = 0; r < K1R; r++) kvpsh[r*HPV3 + c2] = acc[r];
        }
    }
    __syncthreads();

    for (int t = tid; t < K1R*HPV3; t += blockDim.x) {
        int r = t / HPV3, e = t - r*HPV3;
        int kidx = e / 3, x = e % 3;
        int bn = bn0 + r;
        const float* rp = rot + (size_t)bn * 9;
        const float* tp = trans + (size_t)bn * 3;
        float vv = tp[x] * 0.1f;
        #pragma unroll
        for (int y = 0; y < 3; y++) vv += rp[x * 3 + y] * kvpsh[r*HPV3 + kidx * 3 + y];
        g_vg[(size_t)bn * HPV3 + e] = vv;
    }
}

// ================= K2: pair stage (j-tiled GEMM, packed f32x2) =================
// shared layout (floats) — all major regions even-offset for 64-bit LDS
#define OFF_WGT   0          // WgT [64][130] = 8320
#define OFF_W1T   8320       // W1T [64][66]  = 4224 -> 12544
#define OFF_W2T   12544      // W2T [12][66]  = 792  -> 13336
#define OFF_WVL   13344      // 128
#define OFF_MEAN  13472
#define OFF_ISTD  13488
#define OFF_BG    13504
#define OFF_B1    13568
#define OFF_B2    13632
#define OFF_HW    13648
#define OFF_ROTI  13664
#define OFF_TI    13676
#define OFF_QPTS  13680
#define OFF_QVL   13704
#define OFF_MASKI 13728
#define OFF_QI    13732      // 192 -> 13924
#define OFF_VLOC  13924      // [64][25] -> 15524
#define OFF_VLEN  15524      // [64][8]  -> 16036
#define OFF_GAU   16036      // [64][132] -> 24484 (reused for h1)
#define OFF_GB    24484      // [64][68]  -> 28836
#define SMEM2_FLOATS 28836
#define SMEM2_BYTES  (SMEM2_FLOATS * 4)
#define JT 64

__global__ void k2_pair(const float* __restrict__ rot,
                        const float* __restrict__ trans,
                        const float* __restrict__ mask,
                        const float* __restrict__ head_weights,
                        const float* __restrict__ Wvl,
                        const float* __restrict__ gbf_means,
                        const float* __restrict__ gbf_stds,
                        const float* __restrict__ Wg, const float* __restrict__ bg,
                        const float* __restrict__ W1, const float* __restrict__ b1,
                        const float* __restrict__ W2, const float* __restrict__ b2,
                        float* __restrict__ g_out)
{
    extern __shared__ float sh[];
    int bi = blockIdx.x;
    int b = bi >> 9, i = bi & 511;
    int tid = threadIdx.x;

    // transposed weight loads (coalesced global reads)
    for (int t = tid; t < 8192; t += 256) {
        int m = t >> 6, c = t & 63;
        sh[OFF_WGT + c*130 + m] = Wg[t];
    }
    for (int t = tid; t < 4096; t += 256) {
        int m = t >> 6, c = t & 63;
        sh[OFF_W1T + c*66 + m] = W1[t];
    }
    for (int t = tid; t < 768; t += 256) {
        int m = t / 12, h = t - m*12;
        sh[OFF_W2T + h*66 + m] = W2[t];
    }
    if (tid < 128) sh[OFF_WVL + tid] = Wvl[tid];
    if (tid < NK) {
        sh[OFF_MEAN + tid] = gbf_means[tid];
        sh[OFF_ISTD + tid] = 1.0f / gbf_stds[tid];
    }
    if (tid < NG) { sh[OFF_BG + tid] = bg[tid]; sh[OFF_B1 + tid] = b1[tid]; }
    if (tid < NH) {
        sh[OFF_B2 + tid] = b2[tid];
        float x = head_weights[tid];
        float sp = logf(1.0f + expf(x));
        sh[OFF_HW + tid] = sp * (-0.11785113f);   // softplus * sqrt(1/18) * -0.5
    }
    if (tid < 9) sh[OFF_ROTI + tid] = rot[(size_t)bi * 9 + tid];
    if (tid < 3) sh[OFF_TI + tid] = trans[(size_t)bi * 3 + tid];
    if (tid < 24) sh[OFF_QPTS + tid] = g_qpts[(size_t)bi * 24 + tid];
    if (tid == 0) sh[OFF_MASKI] = mask[bi];
    if (tid < HC) sh[OFF_QI + tid] = g_q[(size_t)bi * HC + tid];
    __syncthreads();

    if (tid < 24) {  // q-contribution of Wvl (j-independent)
        int o = tid / 3, x = tid % 3;
        float acc = 0.f;
        #pragma unroll
        for (int p = 0; p < NP; p++)
            acc += sh[OFF_WVL + o * 16 + 8 + p] * sh[OFF_QPTS + p * 3 + x];
        sh[OFF_QVL + tid] = acc;
    }
    __syncthreads();

    float ti0 = sh[OFF_TI + 0], ti1 = sh[OFF_TI + 1], ti2 = sh[OFF_TI + 2];
    float mi = sh[OFF_MASKI];
    int ty = tid >> 4, tx = tid & 15;

    for (int j0 = 0; j0 < NN; j0 += JT) {
        // ---- A: v_loc ----
        {
            int jj = tid >> 2, qq = tid & 3;
            int j = j0 + jj;
            const float* rj = rot + ((size_t)b * NN + j) * 9;
            const float* tj = trans + ((size_t)b * NN + j) * 3;
            float R[3][3], tr[3];
            #pragma unroll
            for (int x = 0; x < 3; x++) {
                float a0 = sh[OFF_ROTI + 0*3 + x];
                float a1 = sh[OFF_ROTI + 1*3 + x];
                float a2 = sh[OFF_ROTI + 2*3 + x];
                #pragma unroll
                for (int z = 0; z < 3; z++)
                    R[x][z] = a0 * rj[0*3+z] + a1 * rj[1*3+z] + a2 * rj[2*3+z];
                tr[x] = a0 * (tj[0] - ti0) + a1 * (tj[1] - ti1) + a2 * (tj[2] - ti2);
            }
            #pragma unroll
            for (int pp = 0; pp < 2; pp++) {
                int p = qq * 2 + pp;
                const float* vp = g_vpts + ((size_t)b * NN + j) * 24 + p * 3;
                float v0 = vp[0], v1 = vp[1], v2 = vp[2];
                #pragma unroll
                for (int x = 0; x < 3; x++)
                    sh[OFF_VLOC + jj*25 + p*3 + x] = R[x][0]*v0 + R[x][1]*v1 + R[x][2]*v2 + tr[x];
            }
        }
        __syncthreads();
        // ---- B: vec + vlen ----
        {
            int jj = tid >> 2, qq = tid & 3;
            const float* vl = sh + OFF_VLOC + jj*25;
            #pragma unroll
            for (int oo = 0; oo < 2; oo++) {
                int o = qq * 2 + oo;
                float vx = sh[OFF_QVL + o*3+0] + vl[o*3+0];
                float vy = sh[OFF_QVL + o*3+1] + vl[o*3+1];
                float vz = sh[OFF_QVL + o*3+2] + vl[o*3+2];
                #pragma unroll
                for (int p = 0; p < NP; p++) {
                    float w_ = sh[OFF_WVL + o * 16 + p];
                    vx += w_ * vl[p*3+0];
                    vy += w_ * vl[p*3+1];
                    vz += w_ * vl[p*3+2];
                }
                sh[OFF_VLEN + jj*8 + o] = sqrtf(vx*vx + vy*vy + vz*vz + 1e-8f);
            }
        }
        __syncthreads();
        // ---- C: gauss [64][128] ----
        #pragma unroll
        for (int it = 0; it < 32; it++) {
            int flat = tid + 256 * it;
            int jj = flat >> 7, m = flat & 127;
            int p = m >> 4, kk = m & 15;
            float d = (sh[OFF_VLEN + jj*8 + p] - sh[OFF_MEAN + kk]) * sh[OFF_ISTD + kk];
            sh[OFF_GAU + jj*132 + m] = __expf(-0.5f * d * d);
        }
        __syncthreads();
        // ---- D: g[64][64] = gauss @ Wg + bg (packed f32x2, k-paired) ----
        {
            unsigned long long acc2[4][4];
            #pragma unroll
            for (int r = 0; r < 4; r++)
                #pragma unroll
                for (int c = 0; c < 4; c++) acc2[r][c] = 0ULL;
            const unsigned long long* gp0 = (const unsigned long long*)(sh + OFF_GAU + (4*ty+0)*132);
            const unsigned long long* gp1 = (const unsigned long long*)(sh + OFF_GAU + (4*ty+1)*132);
            const unsigned long long* gp2 = (const unsigned long long*)(sh + OFF_GAU + (4*ty+2)*132);
            const unsigned long long* gp3 = (const unsigned long long*)(sh + OFF_GAU + (4*ty+3)*132);
            const unsigned long long* wp0 = (const unsigned long long*)(sh + OFF_WGT + (tx*4+0)*130);
            const unsigned long long* wp1 = (const unsigned long long*)(sh + OFF_WGT + (tx*4+1)*130);
            const unsigned long long* wp2 = (const unsigned long long*)(sh + OFF_WGT + (tx*4+2)*130);
            const unsigned long long* wp3 = (const unsigned long long*)(sh + OFF_WGT + (tx*4+3)*130);
            #pragma unroll 4
            for (int m2 = 0; m2 < 64; m2++) {
                unsigned long long w0 = wp0[m2], w1 = wp1[m2], w2 = wp2[m2], w3 = wp3[m2];
                unsigned long long a0 = gp0[m2], a1 = gp1[m2], a2 = gp2[m2], a3 = gp3[m2];
                FFMA2(acc2[0][0], a0, w0, acc2[0][0]); FFMA2(acc2[0][1], a0, w1, acc2[0][1]);
                FFMA2(acc2[0][2], a0, w2, acc2[0][2]); FFMA2(acc2[0][3], a0, w3, acc2[0][3]);
                FFMA2(acc2[1][0], a1, w0, acc2[1][0]); FFMA2(acc2[1][1], a1, w1, acc2[1][1]);
                FFMA2(acc2[1][2], a1, w2, acc2[1][2]); FFMA2(acc2[1][3], a1, w3, acc2[1][3]);
                FFMA2(acc2[2][0], a2, w0, acc2[2][0]); FFMA2(acc2[2][1], a2, w1, acc2[2][1]);
                FFMA2(acc2[2][2], a2, w2, acc2[2][2]); FFMA2(acc2[2][3], a2, w3, acc2[2][3]);
                FFMA2(acc2[3][0], a3, w0, acc2[3][0]); FFMA2(acc2[3][1], a3, w1, acc2[3][1]);
                FFMA2(acc2[3][2], a3, w2, acc2[3][2]); FFMA2(acc2[3][3], a3, w3, acc2[3][3]);
            }
            #pragma unroll
            for (int r = 0; r < 4; r++) {
                int jj = 4*ty + r;
                float res[4];
                #pragma unroll
                for (int c = 0; c < 4; c++) {
                    float lo, hi;
                    UNPACK2(lo, hi, acc2[r][c]);
                    res[c] = lo + hi + sh[OFF_BG + tx*4 + c];
                }
                float4 v4 = make_float4(res[0], res[1], res[2], res[3]);
                *(float4*)(sh + OFF_GB + jj*68 + tx*4) = v4;
                *(float4*)(g_out + ((size_t)bi * NN + j0 + jj) * NG + tx*4) = v4;
            }
        }
        __syncthreads();
        // ---- E: h1[64][64] = relu(g @ W1 + b1) (packed f32x2) ----
        {
            unsigned long long acc2[4][4];
            #pragma unroll
            for (int r = 0; r < 4; r++)
                #pragma unroll
                for (int c = 0; c < 4; c++) acc2[r][c] = 0ULL;
            const unsigned long long* gp0 = (const unsigned long long*)(sh + OFF_GB + (4*ty+0)*68);
            const unsigned long long* gp1 = (const unsigned long long*)(sh + OFF_GB + (4*ty+1)*68);
            const unsigned long long* gp2 = (const unsigned long long*)(sh + OFF_GB + (4*ty+2)*68);
            const unsigned long long* gp3 = (const unsigned long long*)(sh + OFF_GB + (4*ty+3)*68);
            const unsigned long long* wp0 = (const unsigned long long*)(sh + OFF_W1T + (tx*4+0)*66);
            const unsigned long long* wp1 = (const unsigned long long*)(sh + OFF_W1T + (tx*4+1)*66);
            const unsigned long long* wp2 = (const unsigned long long*)(sh + OFF_W1T + (tx*4+2)*66);
            const unsigned long long* wp3 = (const unsigned long long*)(sh + OFF_W1T + (tx*4+3)*66);
            #pragma unroll 4
            for (int m2 = 0; m2 < 32; m2++) {
                unsigned long long w0 = wp0[m2], w1 = wp1[m2], w2 = wp2[m2], w3 = wp3[m2];
                unsigned long long a0 = gp0[m2], a1 = gp1[m2], a2 = gp2[m2], a3 = gp3[m2];
                FFMA2(acc2[0][0], a0, w0, acc2[0][0]); FFMA2(acc2[0][1], a0, w1, acc2[0][1]);
                FFMA2(acc2[0][2], a0, w2, acc2[0][2]); FFMA2(acc2[0][3], a0, w3, acc2[0][3]);
                FFMA2(acc2[1][0], a1, w0, acc2[1][0]); FFMA2(acc2[1][1], a1, w1, acc2[1][1]);
                FFMA2(acc2[1][2], a1, w2, acc2[1][2]); FFMA2(acc2[1][3], a1, w3, acc2[1][3]);
                FFMA2(acc2[2][0], a2, w0, acc2[2][0]); FFMA2(acc2[2][1], a2, w1, acc2[2][1]);
                FFMA2(acc2[2][2], a2, w2, acc2[2][2]); FFMA2(acc2[2][3], a2, w3, acc2[2][3]);
                FFMA2(acc2[3][0], a3, w0, acc2[3][0]); FFMA2(acc2[3][1], a3, w1, acc2[3][1]);
                FFMA2(acc2[3][2], a3, w2, acc2[3][2]); FFMA2(acc2[3][3], a3, w3, acc2[3][3]);
            }
            __syncthreads();   // gauss fully consumed; safe to overwrite GAU with h1
            #pragma unroll
            for (int r = 0; r < 4; r++) {
                int jj = 4*ty + r;
                float res[4];
                #pragma unroll
                for (int c = 0; c < 4; c++) {
                    float lo, hi;
                    UNPACK2(lo, hi, acc2[r][c]);
                    res[c] = fmaxf(lo + hi + sh[OFF_B1 + tx*4 + c], 0.f);
                }
                *(float4*)(sh + OFF_GAU + jj*132 + tx*4) =
                    make_float4(res[0], res[1], res[2], res[3]);
            }
        }
        __syncthreads();
        // ---- F: vfn + qk + dist -> logits (packed f32x2 for vfn) ----
        for (int idx = tid; idx < JT * NH; idx += 256) {
            int jj = idx / NH, h = idx - jj * NH;
            int j = j0 + jj;
            const unsigned long long* h1p = (const unsigned long long*)(sh + OFF_GAU + jj*132);
            const unsigned long long* w2p = (const unsigned long long*)(sh + OFF_W2T + h*66);
            unsigned long long acc2 = 0ULL;
            #pragma unroll 8
            for (int m2 = 0; m2 < 32; m2++)
                FFMA2(acc2, h1p[m2], w2p[m2], acc2);
            float lo, hi;
            UNPACK2(lo, hi, acc2);
            float acc = lo + hi + sh[OFF_B2 + h];
            const float4* kp = (const float4*)(g_k + ((size_t)b * NN + j) * HC + h * NC);
            const float4* qp = (const float4*)(sh + OFF_QI + h * NC);
            float qk = 0.f;
            #pragma unroll
            for (int c = 0; c < 4; c++) {
                float4 kk4 = kp[c], qq4 = qp[c];
                qk += qq4.x*kk4.x + qq4.y*kk4.y + qq4.z*kk4.z + qq4.w*kk4.w;
            }
            const float* tj = trans + ((size_t)b * NN + j) * 3;
            float d0 = (tj[0] - ti0) * 0.1f;
            float d1 = (tj[1] - ti1) * 0.1f;
            float d2 = (tj[2] - ti2) * 0.1f;
            float pd = d0*d0 + d1*d1 + d2*d2;
            float mj = mask[(size_t)b * NN + j];
            float logit = qk * 0.125f + acc * 0.5f + pd * sh[OFF_HW + h]
                        + 100000.0f * (mi * mj - 1.0f);
            g_logits[((((size_t)b * NH + h) * NN) + i) * NN + j] = logit;
        }
        __syncthreads();
    }
}

// ================= K4: fused softmax + attention-weighted sums =================
// block = (b, h, itile of 32); dynamic smem: A [32][520] + V [64][41]
#define K4_AST 520
#define K4_SMEM_FLOATS (32*K4_AST + 64*41)
#define K4_SMEM_BYTES  (K4_SMEM_FLOATS * 4)
__global__ void k4_attn()
{
    extern __shared__ float sh4[];
    float* a_sh = sh4;                 // [32][520]
    float* v_sh = sh4 + 32*K4_AST;     // [64][41]

    int blk = blockIdx.x;
    int it = blk & 15;
    int h  = (blk >> 4) % 12;
    int b  = blk / (16 * 12);
    int i0 = it * 32;
    int tid = threadIdx.x;

    const float* Arow = g_logits + (((size_t)b * NH + h) * NN + i0) * NN;

    // load A tile [32][512]
    for (int idx = tid; idx < 32*512; idx += 256) {
        int ii = idx >> 9, jj = idx & 511;
        a_sh[ii*K4_AST + jj] = Arow[(size_t)ii * NN + jj];
    }
    __syncthreads();

    // fused softmax: 8 threads per row
    {
        int r = tid >> 3, t8 = tid & 7;
        float* row = a_sh + r * K4_AST;
        float mx = -1e30f;
        for (int jj = t8; jj < 512; jj += 8) mx = fmaxf(mx, row[jj]);
        #pragma unroll
        for (int o = 4; o > 0; o >>= 1) mx = fmaxf(mx, __shfl_xor_sync(0xffffffffu, mx, o));
        float sm = 0.f;
        for (int jj = t8; jj < 512; jj += 8) {
            float e = __expf(row[jj] - mx);
            row[jj] = e;
            sm += e;
        }
        #pragma unroll
        for (int o = 4; o > 0; o >>= 1) sm += __shfl_xor_sync(0xffffffffu, sm, o);
        float inv = 1.0f / sm;
        for (int jj = t8; jj < 512; jj += 8) row[jj] *= inv;
    }
    __syncthreads();

    int q  = tid & 7;        // 5 cols each
    int ip = tid >> 3;       // i row
    float acc[5];
    #pragma unroll
    for (int c = 0; c < 5; c++) acc[c] = 0.f;

    for (int jt = 0; jt < NN; jt += 64) {
        for (int idx = tid; idx < 64*40; idx += 256) {
            int jj = idx / 40, c = idx - jj*40;
            int j = jt + jj;
            float v;
            if (c < 16) v = g_v [((size_t)b * NN + j) * HC   + h * NC + c];
            else        v = g_vg[((size_t)b * NN + j) * HPV3 + h * 24 + (c - 16)];
            v_sh[jj*41 + c] = v;
        }
        __syncthreads();
        const float* arow = a_sh + ip*K4_AST + jt;
        #pragma unroll 4
        for (int jj = 0; jj < 64; jj++) {
            float a0 = arow[jj];
            const float* vp = v_sh + jj*41 + q*5;
            #pragma unroll
            for (int c = 0; c < 5; c++) acc[c] += a0 * vp[c];
        }
        __syncthreads();
    }

    int ig = i0 + ip;
    #pragma unroll
    for (int c = 0; c < 5; c++) {
        int col = q*5 + c;
        if (col < 16) g_o  [((size_t)b * NN + ig) * HC   + h * NC + col]      = acc[c];
        else          g_opt[((size_t)b * NN + ig) * HPV3 + h * 24 + (col-16)] = acc[c];
    }
}

// ================= K5: final features + output GEMV, 8 rows/block =================
#define K5R 8
__global__ void k5_out(const float* __restrict__ rot,
                       const float* __restrict__ trans,
                       const float* __restrict__ Wout,
                       const float* __restrict__ bout,
                       float* __restrict__ sout)
{
    __shared__ float feats[K5R*576];
    int bi0 = blockIdx.x * K5R;
    int tid = threadIdx.x;

    for (int idx = tid; idx < K5R*HC; idx += 384) {
        int r = idx / HC, c = idx - r*HC;
        feats[r*576 + c] = g_o[(size_t)(bi0+r) * HC + c];
    }
    for (int idx = tid; idx < K5R*96; idx += 384) {
        int r = idx / 96, kidx = idx - r*96;
        int bi = bi0 + r;
        const float* rp = rot + (size_t)bi * 9;
        const float* tp = trans + (size_t)bi * 3;
        float oy0 = g_opt[(size_t)bi * HPV3 + kidx*3+0] - tp[0] * 0.1f;
        float oy1 = g_opt[(size_t)bi * HPV3 + kidx*3+1] - tp[1] * 0.1f;
        float oy2 = g_opt[(size_t)bi * HPV3 + kidx*3+2] - tp[2] * 0.1f;
        float l0 = rp[0]*oy0 + rp[3]*oy1 + rp[6]*oy2;
        float l1 = rp[1]*oy0 + rp[4]*oy1 + rp[7]*oy2;
        float l2 = rp[2]*oy0 + rp[5]*oy1 + rp[8]*oy2;
        feats[r*576 + 192 + kidx] = l0;
        feats[r*576 + 288 + kidx] = l1;
        feats[r*576 + 384 + kidx] = l2;
        feats[r*576 + 480 + kidx] = sqrtf(l0*l0 + l1*l1 + l2*l2 + 1e-8f);
    }
    __syncthreads();

    int cs = tid;  // blockDim = 384
    float acc[K5R];
    float bb = bout[cs];
    #pragma unroll
    for (int r = 0; r < K5R; r++) acc[r] = bb;
    for (int f = 0; f < 576; f++) {
        float w = Wout[(size_t)f * CSD + cs];
        #pragma unroll
        for (int r = 0; r < K5R; r++) acc[r] += feats[r*576 + f] * w;
    }
    #pragma unroll
    for (int r = 0; r < K5R; r++)
        sout[(size_t)(bi0+r) * CSD + cs] = acc[r];
}

// ================= launch =================
extern "C" void kernel_launch(void* const* d_in, const int* in_sizes, int n_in,
                              void* d_out, int out_size)
{
    const float* s        = (const float*)d_in[0];
    const float* rot      = (const float*)d_in[1];
    const float* trans    = (const float*)d_in[2];
    const float* mask     = (const float*)d_in[3];
    const float* Wq       = (const float*)d_in[4];
    const float* bq       = (const float*)d_in[5];
    const float* Wkv      = (const float*)d_in[6];
    const float* bkv      = (const float*)d_in[7];
    const float* head_w   = (const float*)d_in[8];
    const float* ln_g     = (const float*)d_in[9];
    const float* ln_b     = (const float*)d_in[10];
    const float* Wpq      = (const float*)d_in[11];
    const float* bpq      = (const float*)d_in[12];
    const float* Wpv      = (const float*)d_in[13];
    const float* bpv      = (const float*)d_in[14];
    const float* Wvl      = (const float*)d_in[15];
    const float* gbf_mean = (const float*)d_in[16];
    const float* gbf_std  = (const float*)d_in[17];
    const float* Wg       = (const float*)d_in[18];
    const float* bg       = (const float*)d_in[19];
    const float* W1       = (const float*)d_in[20];
    const float* b1       = (const float*)d_in[21];
    const float* W2       = (const float*)d_in[22];
    const float* b2       = (const float*)d_in[23];
    const float* Wkvp     = (const float*)d_in[24];
    const float* bkvp     = (const float*)d_in[25];
    const float* Wout     = (const float*)d_in[26];
    const float* bout     = (const float*)d_in[27];

    float* out = (float*)d_out;
    float* sout_part = out;                              // (B,N,CS)
    float* g_part = out + (size_t)NB * NN * CSD;         // (B,N,N,G)

    cudaFuncSetAttribute((const void*)k2_pair,
                         cudaFuncAttributeMaxDynamicSharedMemorySize, SMEM2_BYTES);
    cudaFuncSetAttribute((const void*)k4_attn,
                         cudaFuncAttributeMaxDynamicSharedMemorySize, K4_SMEM_BYTES);

    k1_project<<<NB * NN / K1R, 256>>>(s, rot, trans, Wq, bq, Wkv, bkv,
                                       ln_g, ln_b, Wpq, bpq, Wpv, bpv, Wkvp, bkvp);
    k2_pair<<<NB * NN, 256, SMEM2_BYTES>>>(rot, trans, mask, head_w, Wvl,
                                           gbf_mean, gbf_std, Wg, bg, W1, b1,
                                           W2, b2, g_part);
    k4_attn<<<NB * NH * (NN/32), 256, K4_SMEM_BYTES>>>();
    k5_out<<<NB * NN / K5R, 384>>>(rot, trans, Wout, bout, sout_part);
}

// round 5
// speedup vs baseline: 1.0014x; 1.0014x over previous
#include <cuda_runtime.h>
#include <math.h>

// Problem dims
#define NB 2
#define NN 512
#define CSD 384
#define NH 12
#define NC 16
#define NP 8
#define NPV 8
#define NK 16
#define NG 64
#define HC (NH*NC)          // 192
#define HPV3 (NH*NPV*3)     // 288

// Packed f32x2 FMA (Blackwell, PTX-only)
#define FFMA2(d, a, b, c) \
    asm("fma.rn.f32x2 %0, %1, %2, %3;" : "=l"(d) : "l"(a), "l"(b), "l"(c))
#define UNPACK2(lo, hi, v) \
    asm("mov.b64 {%0, %1}, %2;" : "=f"(lo), "=f"(hi) : "l"(v))

// ---------------- scratch (device globals) -------------
__device__ __align__(16) float g_q   [NB*NN*HC];
__device__ __align__(16) float g_k   [NB*NN*HC];
__device__ __align__(16) float g_v   [NB*NN*HC];
__device__ __align__(16) float g_qpts[NB*NN*NP*3];
__device__ __align__(16) float g_vpts[NB*NN*NP*3];
__device__ __align__(16) float g_vg  [NB*NN*HPV3];
__device__ __align__(16) float g_logits[(size_t)NB*NH*NN*NN];
__device__ __align__(16) float g_o   [NB*NN*HC];
__device__ __align__(16) float g_opt [NB*NN*HPV3];

// ================= K1: per-row projections, 8 rows per block =================
#define K1R 8
__global__ void k1_project(const float* __restrict__ s,
                           const float* __restrict__ rot,
                           const float* __restrict__ trans,
                           const float* __restrict__ Wq,  const float* __restrict__ bq,
                           const float* __restrict__ Wkv, const float* __restrict__ bkv,
                           const float* __restrict__ ln_g,const float* __restrict__ ln_b,
                           const float* __restrict__ Wpq, const float* __restrict__ bpq,
                           const float* __restrict__ Wpv, const float* __restrict__ bpv,
                           const float* __restrict__ Wkvp,const float* __restrict__ bkvp)
{
    __shared__ float ssh [K1R*CSD];
    __shared__ float snsh[K1R*CSD];
    __shared__ float kvpsh[K1R*HPV3];

    int bn0 = blockIdx.x * K1R;
    int tid = threadIdx.x;
    int wid = tid >> 5, lane = tid & 31;

    for (int idx = tid; idx < K1R*CSD; idx += blockDim.x)
        ssh[idx] = s[(size_t)bn0 * CSD + idx];
    __syncthreads();

    {
        int r = wid;
        const float* row = ssh + r * CSD;
        float lsum = 0.f;
        for (int i = lane; i < CSD; i += 32) lsum += row[i];
        #pragma unroll
        for (int o = 16; o > 0; o >>= 1) lsum += __shfl_xor_sync(0xffffffffu, lsum, o);
        float mean = lsum * (1.0f / CSD);
        float lvar = 0.f;
        for (int i = lane; i < CSD; i += 32) { float d = row[i] - mean; lvar += d * d; }
        #pragma unroll
        for (int o = 16; o > 0; o >>= 1) lvar += __shfl_xor_sync(0xffffffffu, lvar, o);
        float inv = rsqrtf(lvar * (1.0f / CSD) + 1e-5f);
        for (int i = lane; i < CSD; i += 32)
            snsh[r * CSD + i] = (row[i] - mean) * inv * ln_g[i] + ln_b[i];
    }
    __syncthreads();

    for (int col = tid; col < 912; col += blockDim.x) {
        float acc[K1R];
        if (col < HC) {
            #pragma unroll
            for (int r = 0; r < K1R; r++) acc[r] = bq[col];
            for (int cs = 0; cs < CSD; cs++) {
                float w = Wq[(size_t)cs * HC + col];
                #pragma unroll
                for (int r = 0; r < K1R; r++) acc[r] += ssh[r*CSD+cs] * w;
            }
            #pragma unroll
            for (int r = 0; r < K1R; r++) g_q[(size_t)(bn0+r) * HC + col] = acc[r];
        } else if (col < 3*HC) {
            int j2 = col - HC;
            #pragma unroll
            for (int r = 0; r < K1R; r++) acc[r] = bkv[j2];
            for (int cs = 0; cs < CSD; cs++) {
                float w = Wkv[(size_t)cs * (2*HC) + j2];
                #pragma unroll
                for (int r = 0; r < K1R; r++) acc[r] += ssh[r*CSD+cs] * w;
            }
            int h = j2 >> 5, rr = j2 & 31;
            #pragma unroll
            for (int r = 0; r < K1R; r++) {
                if (rr < NC) g_k[(size_t)(bn0+r) * HC + h * NC + rr] = acc[r];
                else         g_v[(size_t)(bn0+r) * HC + h * NC + (rr - NC)] = acc[r];
            }
        } else if (col < 600) {
            int c2 = col - 576;
            #pragma unroll
            for (int r = 0; r < K1R; r++) acc[r] = bpq[c2];
            for (int cs = 0; cs < CSD; cs++) {
                float w = Wpq[(size_t)cs * (NP*3) + c2];
                #pragma unroll
                for (int r = 0; r < K1R; r++) acc[r] += snsh[r*CSD+cs] * w;
            }
            #pragma unroll
            for (int r = 0; r < K1R; r++) g_qpts[(size_t)(bn0+r) * (NP*3) + c2] = acc[r];
        } else if (col < 624) {
            int c2 = col - 600;
            #pragma unroll
            for (int r = 0; r < K1R; r++) acc[r] = bpv[c2];
            for (int cs = 0; cs < CSD; cs++) {
                float w = Wpv[(size_t)cs * (NP*3) + c2];
                #pragma unroll
                for (int r = 0; r < K1R; r++) acc[r] += snsh[r*CSD+cs] * w;
            }
            #pragma unroll
            for (int r = 0; r < K1R; r++) g_vpts[(size_t)(bn0+r) * (NP*3) + c2] = acc[r];
        } else {
            int c2 = col - 624;
            #pragma unroll
            for (int r = 0; r < K1R; r++) acc[r] = bkvp[c2];
            for (int cs = 0; cs < CSD; cs++) {
                float w = Wkvp[(size_t)cs * HPV3 + c2];
                #pragma unroll
                for (int r = 0; r < K1R; r++) acc[r] += ssh[r*CSD+cs] * w;
            }
            #pragma unroll
            for (int r = 0; r < K1R; r++) kvpsh[r*HPV3 + c2] = acc[r];
        }
    }
    __syncthreads();

    for (int t = tid; t < K1R*HPV3; t += blockDim.x) {
        int r = t / HPV3, e = t - r*HPV3;
        int kidx = e / 3, x = e % 3;
        int bn = bn0 + r;
        const float* rp = rot + (size_t)bn * 9;
        const float* tp = trans + (size_t)bn * 3;
        float vv = tp[x] * 0.1f;
        #pragma unroll
        for (int y = 0; y < 3; y++) vv += rp[x * 3 + y] * kvpsh[r*HPV3 + kidx * 3 + y];
        g_vg[(size_t)bn * HPV3 + e] = vv;
    }
}

// ================= K2: pair stage (j-tiled GEMM, packed f32x2) =================
// shared layout (floats) — all major regions even-offset for 64-bit LDS
#define OFF_WGT   0          // WgT [64][130] = 8320
#define OFF_W1T   8320       // W1T [64][66]  = 4224 -> 12544
#define OFF_W2T   12544      // W2T [12][66]  = 792  -> 13336
#define OFF_WVL   13344      // 128
#define OFF_MEAN  13472
#define OFF_ISTD  13488
#define OFF_BG    13504
#define OFF_B1    13568
#define OFF_B2    13632
#define OFF_HW    13648
#define OFF_ROTI  13664
#define OFF_TI    13676
#define OFF_QPTS  13680
#define OFF_QVL   13704
#define OFF_MASKI 13728
#define OFF_QI    13732      // 192 -> 13924
#define OFF_VLOC  13924      // [64][25] -> 15524
#define OFF_VLEN  15524      // [64][8]  -> 16036
#define OFF_GAU   16036      // [64][132] -> 24484 (reused for h1)
#define OFF_GB    24484      // [64][68]  -> 28836
#define SMEM2_FLOATS 28836
#define SMEM2_BYTES  (SMEM2_FLOATS * 4)
#define JT 64

__global__ void k2_pair(const float* __restrict__ rot,
                        const float* __restrict__ trans,
                        const float* __restrict__ mask,
                        const float* __restrict__ head_weights,
                        const float* __restrict__ Wvl,
                        const float* __restrict__ gbf_means,
                        const float* __restrict__ gbf_stds,
                        const float* __restrict__ Wg, const float* __restrict__ bg,
                        const float* __restrict__ W1, const float* __restrict__ b1,
                        const float* __restrict__ W2, const float* __restrict__ b2,
                        float* __restrict__ g_out)
{
    extern __shared__ float sh[];
    int bi = blockIdx.x;
    int b = bi >> 9, i = bi & 511;
    int tid = threadIdx.x;

    // transposed weight loads (coalesced global reads)
    for (int t = tid; t < 8192; t += 256) {
        int m = t >> 6, c = t & 63;
        sh[OFF_WGT + c*130 + m] = Wg[t];
    }
    for (int t = tid; t < 4096; t += 256) {
        int m = t >> 6, c = t & 63;
        sh[OFF_W1T + c*66 + m] = W1[t];
    }
    for (int t = tid; t < 768; t += 256) {
        int m = t / 12, h = t - m*12;
        sh[OFF_W2T + h*66 + m] = W2[t];
    }
    if (tid < 128) sh[OFF_WVL + tid] = Wvl[tid];
    if (tid < NK) {
        sh[OFF_MEAN + tid] = gbf_means[tid];
        sh[OFF_ISTD + tid] = 1.0f / gbf_stds[tid];
    }
    if (tid < NG) { sh[OFF_BG + tid] = bg[tid]; sh[OFF_B1 + tid] = b1[tid]; }
    if (tid < NH) {
        sh[OFF_B2 + tid] = b2[tid];
        float x = head_weights[tid];
        float sp = logf(1.0f + expf(x));
        sh[OFF_HW + tid] = sp * (-0.11785113f);   // softplus * sqrt(1/18) * -0.5
    }
    if (tid < 9) sh[OFF_ROTI + tid] = rot[(size_t)bi * 9 + tid];
    if (tid < 3) sh[OFF_TI + tid] = trans[(size_t)bi * 3 + tid];
    if (tid < 24) sh[OFF_QPTS + tid] = g_qpts[(size_t)bi * 24 + tid];
    if (tid == 0) sh[OFF_MASKI] = mask[bi];
    if (tid < HC) sh[OFF_QI + tid] = g_q[(size_t)bi * HC + tid];
    __syncthreads();

    if (tid < 24) {  // q-contribution of Wvl (j-independent)
        int o = tid / 3, x = tid % 3;
        float acc = 0.f;
        #pragma unroll
        for (int p = 0; p < NP; p++)
            acc += sh[OFF_WVL + o * 16 + 8 + p] * sh[OFF_QPTS + p * 3 + x];
        sh[OFF_QVL + tid] = acc;
    }
    __syncthreads();

    float ti0 = sh[OFF_TI + 0], ti1 = sh[OFF_TI + 1], ti2 = sh[OFF_TI + 2];
    float mi = sh[OFF_MASKI];
    int ty = tid >> 4, tx = tid & 15;

    for (int j0 = 0; j0 < NN; j0 += JT) {
        // ---- A: v_loc ----
        {
            int jj = tid >> 2, qq = tid & 3;
            int j = j0 + jj;
            const float* rj = rot + ((size_t)b * NN + j) * 9;
            const float* tj = trans + ((size_t)b * NN + j) * 3;
            float R[3][3], tr[3];
            #pragma unroll
            for (int x = 0; x < 3; x++) {
                float a0 = sh[OFF_ROTI + 0*3 + x];
                float a1 = sh[OFF_ROTI + 1*3 + x];
                float a2 = sh[OFF_ROTI + 2*3 + x];
                #pragma unroll
                for (int z = 0; z < 3; z++)
                    R[x][z] = a0 * rj[0*3+z] + a1 * rj[1*3+z] + a2 * rj[2*3+z];
                tr[x] = a0 * (tj[0] - ti0) + a1 * (tj[1] - ti1) + a2 * (tj[2] - ti2);
            }
            #pragma unroll
            for (int pp = 0; pp < 2; pp++) {
                int p = qq * 2 + pp;
                const float* vp = g_vpts + ((size_t)b * NN + j) * 24 + p * 3;
                float v0 = vp[0], v1 = vp[1], v2 = vp[2];
                #pragma unroll
                for (int x = 0; x < 3; x++)
                    sh[OFF_VLOC + jj*25 + p*3 + x] = R[x][0]*v0 + R[x][1]*v1 + R[x][2]*v2 + tr[x];
            }
        }
        __syncthreads();
        // ---- B: vec + vlen ----
        {
            int jj = tid >> 2, qq = tid & 3;
            const float* vl = sh + OFF_VLOC + jj*25;
            #pragma unroll
            for (int oo = 0; oo < 2; oo++) {
                int o = qq * 2 + oo;
                float vx = sh[OFF_QVL + o*3+0] + vl[o*3+0];
                float vy = sh[OFF_QVL + o*3+1] + vl[o*3+1];
                float vz = sh[OFF_QVL + o*3+2] + vl[o*3+2];
                #pragma unroll
                for (int p = 0; p < NP; p++) {
                    float w_ = sh[OFF_WVL + o * 16 + p];
                    vx += w_ * vl[p*3+0];
                    vy += w_ * vl[p*3+1];
                    vz += w_ * vl[p*3+2];
                }
                sh[OFF_VLEN + jj*8 + o] = sqrtf(vx*vx + vy*vy + vz*vz + 1e-8f);
            }
        }
        __syncthreads();
        // ---- C: gauss [64][128] ----
        #pragma unroll
        for (int it = 0; it < 32; it++) {
            int flat = tid + 256 * it;
            int jj = flat >> 7, m = flat & 127;
            int p = m >> 4, kk = m & 15;
            float d = (sh[OFF_VLEN + jj*8 + p] - sh[OFF_MEAN + kk]) * sh[OFF_ISTD + kk];
            sh[OFF_GAU + jj*132 + m] = __expf(-0.5f * d * d);
        }
        __syncthreads();
        // ---- D: g[64][64] = gauss @ Wg + bg (packed f32x2, k-paired) ----
        {
            unsigned long long acc2[4][4];
            #pragma unroll
            for (int r = 0; r < 4; r++)
                #pragma unroll
                for (int c = 0; c < 4; c++) acc2[r][c] = 0ULL;
            const unsigned long long* gp0 = (const unsigned long long*)(sh + OFF_GAU + (4*ty+0)*132);
            const unsigned long long* gp1 = (const unsigned long long*)(sh + OFF_GAU + (4*ty+1)*132);
            const unsigned long long* gp2 = (const unsigned long long*)(sh + OFF_GAU + (4*ty+2)*132);
            const unsigned long long* gp3 = (const unsigned long long*)(sh + OFF_GAU + (4*ty+3)*132);
            const unsigned long long* wp0 = (const unsigned long long*)(sh + OFF_WGT + (tx*4+0)*130);
            const unsigned long long* wp1 = (const unsigned long long*)(sh + OFF_WGT + (tx*4+1)*130);
            const unsigned long long* wp2 = (const unsigned long long*)(sh + OFF_WGT + (tx*4+2)*130);
            const unsigned long long* wp3 = (const unsigned long long*)(sh + OFF_WGT + (tx*4+3)*130);
            #pragma unroll 4
            for (int m2 = 0; m2 < 64; m2++) {
                unsigned long long w0 = wp0[m2], w1 = wp1[m2], w2 = wp2[m2], w3 = wp3[m2];
                unsigned long long a0 = gp0[m2], a1 = gp1[m2], a2 = gp2[m2], a3 = gp3[m2];
                FFMA2(acc2[0][0], a0, w0, acc2[0][0]); FFMA2(acc2[0][1], a0, w1, acc2[0][1]);
                FFMA2(acc2[0][2], a0, w2, acc2[0][2]); FFMA2(acc2[0][3], a0, w3, acc2[0][3]);
                FFMA2(acc2[1][0], a1, w0, acc2[1][0]); FFMA2(acc2[1][1], a1, w1, acc2[1][1]);
                FFMA2(acc2[1][2], a1, w2, acc2[1][2]); FFMA2(acc2[1][3], a1, w3, acc2[1][3]);
                FFMA2(acc2[2][0], a2, w0, acc2[2][0]); FFMA2(acc2[2][1], a2, w1, acc2[2][1]);
                FFMA2(acc2[2][2], a2, w2, acc2[2][2]); FFMA2(acc2[2][3], a2, w3, acc2[2][3]);
                FFMA2(acc2[3][0], a3, w0, acc2[3][0]); FFMA2(acc2[3][1], a3, w1, acc2[3][1]);
                FFMA2(acc2[3][2], a3, w2, acc2[3][2]); FFMA2(acc2[3][3], a3, w3, acc2[3][3]);
            }
            #pragma unroll
            for (int r = 0; r < 4; r++) {
                int jj = 4*ty + r;
                float res[4];
                #pragma unroll
                for (int c = 0; c < 4; c++) {
                    float lo, hi;
                    UNPACK2(lo, hi, acc2[r][c]);
                    res[c] = lo + hi + sh[OFF_BG + tx*4 + c];
                }
                float4 v4 = make_float4(res[0], res[1], res[2], res[3]);
                *(float4*)(sh + OFF_GB + jj*68 + tx*4) = v4;
                *(float4*)(g_out + ((size_t)bi * NN + j0 + jj) * NG + tx*4) = v4;
            }
        }
        __syncthreads();
        // ---- E: h1[64][64] = relu(g @ W1 + b1) (packed f32x2) ----
        {
            unsigned long long acc2[4][4];
            #pragma unroll
            for (int r = 0; r < 4; r++)
                #pragma unroll
                for (int c = 0; c < 4; c++) acc2[r][c] = 0ULL;
            const unsigned long long* gp0 = (const unsigned long long*)(sh + OFF_GB + (4*ty+0)*68);
            const unsigned long long* gp1 = (const unsigned long long*)(sh + OFF_GB + (4*ty+1)*68);
            const unsigned long long* gp2 = (const unsigned long long*)(sh + OFF_GB + (4*ty+2)*68);
            const unsigned long long* gp3 = (const unsigned long long*)(sh + OFF_GB + (4*ty+3)*68);
            const unsigned long long* wp0 = (const unsigned long long*)(sh + OFF_W1T + (tx*4+0)*66);
            const unsigned long long* wp1 = (const unsigned long long*)(sh + OFF_W1T + (tx*4+1)*66);
            const unsigned long long* wp2 = (const unsigned long long*)(sh + OFF_W1T + (tx*4+2)*66);
            const unsigned long long* wp3 = (const unsigned long long*)(sh + OFF_W1T + (tx*4+3)*66);
            #pragma unroll 4
            for (int m2 = 0; m2 < 32; m2++) {
                unsigned long long w0 = wp0[m2], w1 = wp1[m2], w2 = wp2[m2], w3 = wp3[m2];
                unsigned long long a0 = gp0[m2], a1 = gp1[m2], a2 = gp2[m2], a3 = gp3[m2];
                FFMA2(acc2[0][0], a0, w0, acc2[0][0]); FFMA2(acc2[0][1], a0, w1, acc2[0][1]);
                FFMA2(acc2[0][2], a0, w2, acc2[0][2]); FFMA2(acc2[0][3], a0, w3, acc2[0][3]);
                FFMA2(acc2[1][0], a1, w0, acc2[1][0]); FFMA2(acc2[1][1], a1, w1, acc2[1][1]);
                FFMA2(acc2[1][2], a1, w2, acc2[1][2]); FFMA2(acc2[1][3], a1, w3, acc2[1][3]);
                FFMA2(acc2[2][0], a2, w0, acc2[2][0]); FFMA2(acc2[2][1], a2, w1, acc2[2][1]);
                FFMA2(acc2[2][2], a2, w2, acc2[2][2]); FFMA2(acc2[2][3], a2, w3, acc2[2][3]);
                FFMA2(acc2[3][0], a3, w0, acc2[3][0]); FFMA2(acc2[3][1], a3, w1, acc2[3][1]);
                FFMA2(acc2[3][2], a3, w2, acc2[3][2]); FFMA2(acc2[3][3], a3, w3, acc2[3][3]);
            }
            __syncthreads();   // gauss fully consumed; safe to overwrite GAU with h1
            #pragma unroll
            for (int r = 0; r < 4; r++) {
                int jj = 4*ty + r;
                float res[4];
                #pragma unroll
                for (int c = 0; c < 4; c++) {
                    float lo, hi;
                    UNPACK2(lo, hi, acc2[r][c]);
                    res[c] = fmaxf(lo + hi + sh[OFF_B1 + tx*4 + c], 0.f);
                }
                *(float4*)(sh + OFF_GAU + jj*132 + tx*4) =
                    make_float4(res[0], res[1], res[2], res[3]);
            }
        }
        __syncthreads();
        // ---- F: vfn + qk + dist -> logits (packed f32x2 for vfn) ----
        for (int idx = tid; idx < JT * NH; idx += 256) {
            int jj = idx / NH, h = idx - jj * NH;
            int j = j0 + jj;
            const unsigned long long* h1p = (const unsigned long long*)(sh + OFF_GAU + jj*132);
            const unsigned long long* w2p = (const unsigned long long*)(sh + OFF_W2T + h*66);
            unsigned long long acc2 = 0ULL;
            #pragma unroll 8
            for (int m2 = 0; m2 < 32; m2++)
                FFMA2(acc2, h1p[m2], w2p[m2], acc2);
            float lo, hi;
            UNPACK2(lo, hi, acc2);
            float acc = lo + hi + sh[OFF_B2 + h];
            const float4* kp = (const float4*)(g_k + ((size_t)b * NN + j) * HC + h * NC);
            const float4* qp = (const float4*)(sh + OFF_QI + h * NC);
            float qk = 0.f;
            #pragma unroll
            for (int c = 0; c < 4; c++) {
                float4 kk4 = kp[c], qq4 = qp[c];
                qk += qq4.x*kk4.x + qq4.y*kk4.y + qq4.z*kk4.z + qq4.w*kk4.w;
            }
            const float* tj = trans + ((size_t)b * NN + j) * 3;
            float d0 = (tj[0] - ti0) * 0.1f;
            float d1 = (tj[1] - ti1) * 0.1f;
            float d2 = (tj[2] - ti2) * 0.1f;
            float pd = d0*d0 + d1*d1 + d2*d2;
            float mj = mask[(size_t)b * NN + j];
            float logit = qk * 0.125f + acc * 0.5f + pd * sh[OFF_HW + h]
                        + 100000.0f * (mi * mj - 1.0f);
            g_logits[((((size_t)b * NH + h) * NN) + i) * NN + j] = logit;
        }
        __syncthreads();
    }
}

// ================= K4: fused softmax + attention-weighted sums =================
// block = (b, h, itile of 32); dynamic smem: A [32][520] + V [64][41]
#define K4_AST 520
#define K4_SMEM_FLOATS (32*K4_AST + 64*41)
#define K4_SMEM_BYTES  (K4_SMEM_FLOATS * 4)
__global__ void k4_attn()
{
    extern __shared__ float sh4[];
    float* a_sh = sh4;                 // [32][520]
    float* v_sh = sh4 + 32*K4_AST;     // [64][41]

    int blk = blockIdx.x;
    int it = blk & 15;
    int h  = (blk >> 4) % 12;
    int b  = blk / (16 * 12);
    int i0 = it * 32;
    int tid = threadIdx.x;

    const float* Arow = g_logits + (((size_t)b * NH + h) * NN + i0) * NN;

    // load A tile [32][512]
    for (int idx = tid; idx < 32*512; idx += 256) {
        int ii = idx >> 9, jj = idx & 511;
        a_sh[ii*K4_AST + jj] = Arow[(size_t)ii * NN + jj];
    }
    __syncthreads();

    // fused softmax: 8 threads per row
    {
        int r = tid >> 3, t8 = tid & 7;
        float* row = a_sh + r * K4_AST;
        float mx = -1e30f;
        for (int jj = t8; jj < 512; jj += 8) mx = fmaxf(mx, row[jj]);
        #pragma unroll
        for (int o = 4; o > 0; o >>= 1) mx = fmaxf(mx, __shfl_xor_sync(0xffffffffu, mx, o));
        float sm = 0.f;
        for (int jj = t8; jj < 512; jj += 8) {
            float e = __expf(row[jj] - mx);
            row[jj] = e;
            sm += e;
        }
        #pragma unroll
        for (int o = 4; o > 0; o >>= 1) sm += __shfl_xor_sync(0xffffffffu, sm, o);
        float inv = 1.0f / sm;
        for (int jj = t8; jj < 512; jj += 8) row[jj] *= inv;
    }
    __syncthreads();

    int q  = tid & 7;        // 5 cols each
    int ip = tid >> 3;       // i row
    float acc[5];
    #pragma unroll
    for (int c = 0; c < 5; c++) acc[c] = 0.f;

    for (int jt = 0; jt < NN; jt += 64) {
        for (int idx = tid; idx < 64*40; idx += 256) {
            int jj = idx / 40, c = idx - jj*40;
            int j = jt + jj;
            float v;
            if (c < 16) v = g_v [((size_t)b * NN + j) * HC   + h * NC + c];
            else        v = g_vg[((size_t)b * NN + j) * HPV3 + h * 24 + (c - 16)];
            v_sh[jj*41 + c] = v;
        }
        __syncthreads();
        const float* arow = a_sh + ip*K4_AST + jt;
        #pragma unroll 4
        for (int jj = 0; jj < 64; jj++) {
            float a0 = arow[jj];
            const float* vp = v_sh + jj*41 + q*5;
            #pragma unroll
            for (int c = 0; c < 5; c++) acc[c] += a0 * vp[c];
        }
        __syncthreads();
    }

    int ig = i0 + ip;
    #pragma unroll
    for (int c = 0; c < 5; c++) {
        int col = q*5 + c;
        if (col < 16) g_o  [((size_t)b * NN + ig) * HC   + h * NC + col]      = acc[c];
        else          g_opt[((size_t)b * NN + ig) * HPV3 + h * 24 + (col-16)] = acc[c];
    }
}

// ================= K5: final features + output GEMV, 8 rows/block =================
#define K5R 8
__global__ void k5_out(const float* __restrict__ rot,
                       const float* __restrict__ trans,
                       const float* __restrict__ Wout,
                       const float* __restrict__ bout,
                       float* __restrict__ sout)
{
    __shared__ float feats[K5R*576];
    int bi0 = blockIdx.x * K5R;
    int tid = threadIdx.x;

    for (int idx = tid; idx < K5R*HC; idx += 384) {
        int r = idx / HC, c = idx - r*HC;
        feats[r*576 + c] = g_o[(size_t)(bi0+r) * HC + c];
    }
    for (int idx = tid; idx < K5R*96; idx += 384) {
        int r = idx / 96, kidx = idx - r*96;
        int bi = bi0 + r;
        const float* rp = rot + (size_t)bi * 9;
        const float* tp = trans + (size_t)bi * 3;
        float oy0 = g_opt[(size_t)bi * HPV3 + kidx*3+0] - tp[0] * 0.1f;
        float oy1 = g_opt[(size_t)bi * HPV3 + kidx*3+1] - tp[1] * 0.1f;
        float oy2 = g_opt[(size_t)bi * HPV3 + kidx*3+2] - tp[2] * 0.1f;
        float l0 = rp[0]*oy0 + rp[3]*oy1 + rp[6]*oy2;
        float l1 = rp[1]*oy0 + rp[4]*oy1 + rp[7]*oy2;
        float l2 = rp[2]*oy0 + rp[5]*oy1 + rp[8]*oy2;
        feats[r*576 + 192 + kidx] = l0;
        feats[r*576 + 288 + kidx] = l1;
        feats[r*576 + 384 + kidx] = l2;
        feats[r*576 + 480 + kidx] = sqrtf(l0*l0 + l1*l1 + l2*l2 + 1e-8f);
    }
    __syncthreads();

    int cs = tid;  // blockDim = 384
    float acc[K5R];
    float bb = bout[cs];
    #pragma unroll
    for (int r = 0; r < K5R; r++) acc[r] = bb;
    for (int f = 0; f < 576; f++) {
        float w = Wout[(size_t)f * CSD + cs];
        #pragma unroll
        for (int r = 0; r < K5R; r++) acc[r] += feats[r*576 + f] * w;
    }
    #pragma unroll
    for (int r = 0; r < K5R; r++)
        sout[(size_t)(bi0+r) * CSD + cs] = acc[r];
}

// ================= launch =================
extern "C" void kernel_launch(void* const* d_in, const int* in_sizes, int n_in,
                              void* d_out, int out_size)
{
    const float* s        = (const float*)d_in[0];
    const float* rot      = (const float*)d_in[1];
    const float* trans    = (const float*)d_in[2];
    const float* mask     = (const float*)d_in[3];
    const float* Wq       = (const float*)d_in[4];
    const float* bq       = (const float*)d_in[5];
    const float* Wkv      = (const float*)d_in[6];
    const float* bkv      = (const float*)d_in[7];
    const float* head_w   = (const float*)d_in[8];
    const float* ln_g     = (const float*)d_in[9];
    const float* ln_b     = (const float*)d_in[10];
    const float* Wpq      = (const float*)d_in[11];
    const float* bpq      = (const float*)d_in[12];
    const float* Wpv      = (const float*)d_in[13];
    const float* bpv      = (const float*)d_in[14];
    const float* Wvl      = (const float*)d_in[15];
    const float* gbf_mean = (const float*)d_in[16];
    const float* gbf_std  = (const float*)d_in[17];
    const float* Wg       = (const float*)d_in[18];
    const float* bg       = (const float*)d_in[19];
    const float* W1       = (const float*)d_in[20];
    const float* b1       = (const float*)d_in[21];
    const float* W2       = (const float*)d_in[22];
    const float* b2       = (const float*)d_in[23];
    const float* Wkvp     = (const float*)d_in[24];
    const float* bkvp     = (const float*)d_in[25];
    const float* Wout     = (const float*)d_in[26];
    const float* bout     = (const float*)d_in[27];

    float* out = (float*)d_out;
    float* sout_part = out;                              // (B,N,CS)
    float* g_part = out + (size_t)NB * NN * CSD;         // (B,N,N,G)

    cudaFuncSetAttribute((const void*)k2_pair,
                         cudaFuncAttributeMaxDynamicSharedMemorySize, SMEM2_BYTES);
    cudaFuncSetAttribute((const void*)k4_attn,
                         cudaFuncAttributeMaxDynamicSharedMemorySize, K4_SMEM_BYTES);

    k1_project<<<NB * NN / K1R, 256>>>(s, rot, trans, Wq, bq, Wkv, bkv,
                                       ln_g, ln_b, Wpq, bpq, Wpv, bpv, Wkvp, bkvp);
    k2_pair<<<NB * NN, 256, SMEM2_BYTES>>>(rot, trans, mask, head_w, Wvl,
                                           gbf_mean, gbf_std, Wg, bg, W1, b1,
                                           W2, b2, g_part);
    k4_attn<<<NB * NH * (NN/32), 256, K4_SMEM_BYTES>>>();
    k5_out<<<NB * NN / K5R, 384>>>(rot, trans, Wout, bout, sout_part);
}